// round 10
// baseline (speedup 1.0000x reference)
#include <cuda_runtime.h>
#include <cstdint>

// ---------------------------------------------------------------------------
// Problem constants
// ---------------------------------------------------------------------------
constexpr int kB   = 8;
constexpr int kN   = 512;
constexpr int kE   = 65536;
constexpr int kNT  = kB * kN;      // 4096
constexpr int kDH  = 64;
constexpr int kR   = 32;

constexpr size_t SZ_NTDH = (size_t)kNT * kDH;     // 262144
constexpr size_t SZ_NTR  = (size_t)kNT * kR;      // 131072
constexpr size_t SZ_S    = (size_t)kB * kN * kN;  // 2097152

constexpr size_t OFF_AGG64S = 0;
constexpr size_t OFF_AGG64T = OFF_AGG64S + SZ_NTDH;
constexpr size_t OFF_AGG32S = OFF_AGG64T + SZ_NTDH;   // 2 slots (steps 0,1)
constexpr size_t OFF_AGG32T = OFF_AGG32S + 2 * SZ_NTR;
constexpr size_t OFF_YS     = OFF_AGG32T + SZ_NTR;
constexpr size_t OFF_YT     = OFF_YS     + SZ_NTDH;
constexpr size_t OFF_HS     = OFF_YT     + SZ_NTDH;
constexpr size_t OFF_HT     = OFF_HS     + SZ_NTDH;
constexpr size_t OFF_SHAT   = OFF_HT     + SZ_NTDH;
constexpr size_t OFF_SNORM  = OFF_SHAT   + SZ_S;
constexpr size_t OFF_RT     = OFF_SNORM  + SZ_S;
constexpr size_t OFF_AS     = OFF_RT     + SZ_NTR;    // 2 steps
constexpr size_t OFF_BT     = OFF_AS     + 2 * SZ_NTR;
constexpr size_t SCRATCH_TOTAL = OFF_BT + SZ_NTR;

__device__ float g_scratch[SCRATCH_TOTAL];

constexpr int NBLK = 384;                 // <= 444 = 148 SMs * 3 blocks
constexpr int NTHR = 256;
constexpr int TOTT = NBLK * NTHR;         // 98304 threads
constexpr int NWARP = NBLK * 8;           // 3072 warps

// Ticket grid barrier (monotonic counter: safe across graph replays)
__device__ unsigned int g_bar = 0;

__device__ __forceinline__ void grid_bar() {
    __syncthreads();
    __threadfence();
    if (threadIdx.x == 0) {
        unsigned old = atomicAdd(&g_bar, 1u);
        unsigned target = (old / NBLK + 1u) * NBLK;
        while (*(volatile unsigned*)&g_bar < target) { }
    }
    __syncthreads();
    __threadfence();
}

__device__ __forceinline__ void red4(float* p, float4 v, float w) {
    asm volatile("red.global.add.v4.f32 [%0], {%1,%2,%3,%4};"
                 :: "l"(p), "f"(v.x * w), "f"(v.y * w), "f"(v.z * w), "f"(v.w * w)
                 : "memory");
}

__device__ __forceinline__ float dot4(float4 a, float4 b, float acc) {
    return fmaf(a.x, b.x, fmaf(a.y, b.y, fmaf(a.z, b.z, fmaf(a.w, b.w, acc))));
}

// ---------------------------------------------------------------------------
// Shared memory layouts (union, 16B-aligned)
// ---------------------------------------------------------------------------
struct RootSm { float As[16][128]; };                               // 8 KB
struct Psi2Sm {                                                     // ~25 KB
    float rsm[8][4][33];
    float gsm[8][4][33];
    float osm[8][4][33];
    float wr[32 * 33];
    float wn[32 * 33];
    float wm[32 * 33];
};
struct GemmSm { float hsS[16][68]; float htS[128][68]; };           // 38.3 KB
struct RtSm   { float St[16][68];  float Rt[32][68]; };             // 12.8 KB
struct MlpSm  { float Bsm[128][36]; float Asm[16][36]; float w2[32]; }; // 20.4 KB

union __align__(16) MegaSm {
    RootSm r; Psi2Sm p; GemmSm g; RtSm a; MlpSm d;
};

// ---------------------------------------------------------------------------
// psi_2 + Wm1 body (weights + operands staged in smem):
//   o = relu( r @ W2_root + agg @ W2_nbr + b2 ); out = o @ Wm1 (+ bm1)
// NOTE: caller must __syncthreads() before calling if smem was in use.
// ---------------------------------------------------------------------------
template<int RPW>
__device__ __forceinline__ void psi2_body(
    Psi2Sm& sm, int row_base,
    const float* __restrict__ r, const float* __restrict__ agg,
    const float* __restrict__ W2_root, const float* __restrict__ W2_nbr,
    const float* __restrict__ b2, const float* __restrict__ Wm1,
    const float* __restrict__ bm1, float* __restrict__ out, int hasBm1)
{
    int tid = threadIdx.x;
    for (int i = tid; i < 1024; i += NTHR) {
        int k = i >> 5, c = i & 31;
        sm.wr[k * 33 + c] = W2_root[i];
        sm.wn[k * 33 + c] = W2_nbr[i];
        sm.wm[k * 33 + c] = Wm1[i];
    }
    int warp = tid >> 5, lane = tid & 31;
    int row0 = row_base + warp * RPW;

    #pragma unroll
    for (int rr = 0; rr < RPW; rr++) {
        sm.rsm[warp][rr][lane] = r[(size_t)(row0 + rr) * 32 + lane];
        sm.gsm[warp][rr][lane] = agg[(size_t)(row0 + rr) * 32 + lane];
    }
    __syncthreads();

    float o[RPW];
    float bv = b2[lane];
    #pragma unroll
    for (int rr = 0; rr < RPW; rr++) o[rr] = bv;
    #pragma unroll 8
    for (int k = 0; k < 32; k++) {
        float wr = sm.wr[k * 33 + lane];
        float wn = sm.wn[k * 33 + lane];
        #pragma unroll
        for (int rr = 0; rr < RPW; rr++) {
            o[rr] = fmaf(sm.rsm[warp][rr][k], wr, o[rr]);
            o[rr] = fmaf(sm.gsm[warp][rr][k], wn, o[rr]);
        }
    }
    #pragma unroll
    for (int rr = 0; rr < RPW; rr++) sm.osm[warp][rr][lane] = fmaxf(o[rr], 0.f);
    __syncwarp();

    float a[RPW];
    float b0 = hasBm1 ? bm1[lane] : 0.f;
    #pragma unroll
    for (int rr = 0; rr < RPW; rr++) a[rr] = b0;
    #pragma unroll 8
    for (int k = 0; k < 32; k++) {
        float w = sm.wm[k * 33 + lane];
        #pragma unroll
        for (int rr = 0; rr < RPW; rr++) a[rr] = fmaf(sm.osm[warp][rr][k], w, a[rr]);
    }
    #pragma unroll
    for (int rr = 0; rr < RPW; rr++) out[(size_t)(row0 + rr) * 32 + lane] = a[rr];
}

// ---------------------------------------------------------------------------
// proj/root GEMM tile: 16 rows x 64 cols, K=128, float4 A reads.
// ---------------------------------------------------------------------------
template<bool RELU, bool HASBIAS, bool HASADD>
__device__ __forceinline__ void rowgemm_tile(
    RootSm& sm, int row0,
    const float* __restrict__ A, const float* __restrict__ W,
    const float* __restrict__ bias, const float* __restrict__ add,
    float* __restrict__ out)
{
    int tid = threadIdx.x;
    const float4* A4 = reinterpret_cast<const float4*>(A + (size_t)row0 * 128);
    __syncthreads();
    for (int i = tid; i < 512; i += NTHR)
        *reinterpret_cast<float4*>(&sm.As[i >> 5][(i & 31) * 4]) = A4[i];
    __syncthreads();

    int j = tid & 63, g = tid >> 6;
    float acc[4];
    float bv = HASBIAS ? bias[j] : 0.f;
    #pragma unroll
    for (int rr = 0; rr < 4; rr++) acc[rr] = bv;

    #pragma unroll 4
    for (int k4 = 0; k4 < 32; k4++) {
        float w0 = __ldg(&W[(k4 * 4 + 0) * 64 + j]);
        float w1 = __ldg(&W[(k4 * 4 + 1) * 64 + j]);
        float w2 = __ldg(&W[(k4 * 4 + 2) * 64 + j]);
        float w3 = __ldg(&W[(k4 * 4 + 3) * 64 + j]);
        #pragma unroll
        for (int rr = 0; rr < 4; rr++) {
            float4 av = *reinterpret_cast<const float4*>(&sm.As[g * 4 + rr][k4 * 4]);
            acc[rr] = fmaf(av.x, w0, fmaf(av.y, w1, fmaf(av.z, w2, fmaf(av.w, w3, acc[rr]))));
        }
    }
    #pragma unroll
    for (int rr = 0; rr < 4; rr++) {
        size_t idx = (size_t)(row0 + g * 4 + rr) * 64 + j;
        float v = acc[rr];
        if (HASADD) v += add[idx];
        if (RELU)   v = fmaxf(v, 0.f);
        out[idx] = v;
    }
}

// ---------------------------------------------------------------------------
// Row softmax pass: warp-strided over all 4096 rows, fully in registers.
// ---------------------------------------------------------------------------
__device__ __forceinline__ void softmax_rows(
    const float* __restrict__ src, float* __restrict__ dst, int gw, int lane)
{
    #pragma unroll 1
    for (int row = gw; row < kNT; row += NWARP) {
        const float4* p = reinterpret_cast<const float4*>(src + (size_t)row * kN);
        float v[16];
        #pragma unroll
        for (int q = 0; q < 4; q++) {
            float4 t = p[lane + 32 * q];
            v[4 * q] = t.x; v[4 * q + 1] = t.y; v[4 * q + 2] = t.z; v[4 * q + 3] = t.w;
        }
        float m = v[0];
        #pragma unroll
        for (int j = 1; j < 16; j++) m = fmaxf(m, v[j]);
        #pragma unroll
        for (int o = 16; o > 0; o >>= 1) m = fmaxf(m, __shfl_xor_sync(0xffffffffu, m, o));
        float s = 0.f;
        #pragma unroll
        for (int j = 0; j < 16; j++) { v[j] = __expf(v[j] - m); s += v[j]; }
        #pragma unroll
        for (int o = 16; o > 0; o >>= 1) s += __shfl_xor_sync(0xffffffffu, s, o);
        float inv = 1.f / s;
        float4* o4 = reinterpret_cast<float4*>(dst + (size_t)row * kN);
        #pragma unroll
        for (int q = 0; q < 4; q++)
            o4[lane + 32 * q] = make_float4(v[4 * q] * inv, v[4 * q + 1] * inv,
                                            v[4 * q + 2] * inv, v[4 * q + 3] * inv);
    }
}

// ---------------------------------------------------------------------------
// THE kernel: 384 blocks x 256 threads, __launch_bounds__(256, 3).
// All phases partitioned over 384 co-resident blocks.
// ---------------------------------------------------------------------------
__global__ __launch_bounds__(256, 3) void mega_kernel(
    const float* __restrict__ x_s, const float* __restrict__ x_t,
    const int* __restrict__ eis, const float* __restrict__ eas,
    const int* __restrict__ eit, const float* __restrict__ eat,
    const float* __restrict__ r_all,
    const float* __restrict__ W1_root, const float* __restrict__ W1_nbr,
    const float* __restrict__ b1,
    const float* __restrict__ W2_root, const float* __restrict__ W2_nbr,
    const float* __restrict__ b2,
    const float* __restrict__ Wm1, const float* __restrict__ bm1,
    const float* __restrict__ Wm2, const float* __restrict__ bm2,
    float* __restrict__ outS0, float* __restrict__ outSL)
{
    __shared__ MegaSm sm;

    int tid = threadIdx.x;
    int bk = blockIdx.x;
    int w = tid >> 5, lane = tid & 31;
    int gw = bk * 8 + w;   // global warp id 0..3071

    float* agg64s = g_scratch + OFF_AGG64S;
    float* agg64t = g_scratch + OFF_AGG64T;
    float* agg32s = g_scratch + OFF_AGG32S;
    float* agg32t = g_scratch + OFF_AGG32T;
    float* ys     = g_scratch + OFF_YS;
    float* yt     = g_scratch + OFF_YT;
    float* hs     = g_scratch + OFF_HS;
    float* ht     = g_scratch + OFF_HT;
    float* Shat   = g_scratch + OFF_SHAT;
    float* Snorm  = g_scratch + OFF_SNORM;
    float* rtbuf  = g_scratch + OFF_RT;
    float* asbuf  = g_scratch + OFF_AS;
    float* btbuf  = g_scratch + OFF_BT;

    // ======== P0: zero atomic buffers + projection y = x @ W1_nbr ========
    {
        float4* z4 = reinterpret_cast<float4*>(agg64s);  // 196608 float4 total
        float4 zz = make_float4(0.f, 0.f, 0.f, 0.f);
        for (int i = bk * NTHR + tid; i < 196608; i += TOTT) z4[i] = zz;
    }
    #pragma unroll 1
    for (int tl = bk; tl < 512; tl += NBLK) {
        int y = tl >> 8;
        rowgemm_tile<false, false, false>(sm.r, (tl & 255) * 16,
                                          y ? x_t : x_s, W1_nbr, nullptr, nullptr,
                                          y ? yt : ys);
    }
    grid_bar();

    // ======== P1: all input-side scatters (atomics, grid-strided) ========
    #pragma unroll 1
    for (int graph = 0; graph < 2; graph++) {
        const float* yy  = graph ? yt : ys;
        const int*   ei  = graph ? eit : eis;
        const float* ea  = graph ? eat : eas;
        float*       agg = graph ? agg64t : agg64s;
        #pragma unroll 1
        for (int gid = bk * NTHR + tid; gid < kE * 16; gid += TOTT) {
            int e = gid >> 4, c = gid & 15;
            int s = ei[e], d = ei[kE + e];
            float wgt = ea[e];
            float4 v = *reinterpret_cast<const float4*>(yy + (size_t)s * 64 + c * 4);
            red4(agg + (size_t)d * 64 + c * 4, v, wgt);
        }
    }
    #pragma unroll 1
    for (int step = 0; step < 2; step++) {
        const float* yy  = r_all  + (size_t)step * SZ_NTR;
        float*       agg = agg32s + (size_t)step * SZ_NTR;
        #pragma unroll 1
        for (int gid = bk * NTHR + tid; gid < kE * 8; gid += TOTT) {
            int e = gid >> 3, c = gid & 7;
            int s = eis[e], d = eis[kE + e];
            float wgt = eas[e];
            float4 v = *reinterpret_cast<const float4*>(yy + (size_t)s * 32 + c * 4);
            red4(agg + (size_t)d * 32 + c * 4, v, wgt);
        }
    }
    grid_bar();

    // ======== P2: root GEMM + a_s psi2 (both steps, 16-row units) ========
    #pragma unroll 1
    for (int tl = bk; tl < 512; tl += NBLK) {
        int y = tl >> 8;
        rowgemm_tile<true, true, true>(sm.r, (tl & 255) * 16,
                                       y ? x_t : x_s, W1_root, b1,
                                       y ? agg64t : agg64s,
                                       y ? ht : hs);
    }
    #pragma unroll 1
    for (int u = bk; u < 512; u += NBLK) {
        int stp = u >> 8;
        __syncthreads();
        psi2_body<2>(sm.p, (u & 255) * 16,
                     r_all + (size_t)stp * SZ_NTR, agg32s + (size_t)stp * SZ_NTR,
                     W2_root, W2_nbr, b2, Wm1, bm1,
                     asbuf + (size_t)stp * SZ_NTR, 1);
    }
    grid_bar();

    // ======== P3: S_hat0 = h_s @ h_t^T, (b, s-tile, t-half) units ========
    #pragma unroll 1
    for (int u = bk; u < 512; u += NBLK) {
        int b  = u >> 6;
        int s0 = ((u >> 1) & 31) * 16;
        int th = u & 1;

        __syncthreads();
        const float4* hsb4 = reinterpret_cast<const float4*>(hs + ((size_t)b * kN + s0) * kDH);
        for (int i = tid; i < 256; i += NTHR)
            *reinterpret_cast<float4*>(&sm.g.hsS[i >> 4][(i & 15) * 4]) = hsb4[i];

        #pragma unroll 1
        for (int tt2 = 0; tt2 < 2; tt2++) {
            int tt = th * 2 + tt2;
            __syncthreads();
            const float4* htb4 = reinterpret_cast<const float4*>(ht + ((size_t)b * kN + tt * 128) * kDH);
            for (int i = tid; i < 2048; i += NTHR)
                *reinterpret_cast<float4*>(&sm.g.htS[i >> 4][(i & 15) * 4]) = htb4[i];
            __syncthreads();

            float acc[2][4];
            #pragma unroll
            for (int i = 0; i < 2; i++)
                #pragma unroll
                for (int m = 0; m < 4; m++) acc[i][m] = 0.f;

            #pragma unroll 4
            for (int k4 = 0; k4 < 16; k4++) {
                float4 a0 = *reinterpret_cast<const float4*>(&sm.g.hsS[2 * w][k4 * 4]);
                float4 a1 = *reinterpret_cast<const float4*>(&sm.g.hsS[2 * w + 1][k4 * 4]);
                #pragma unroll
                for (int m = 0; m < 4; m++) {
                    float4 hv = *reinterpret_cast<const float4*>(&sm.g.htS[lane + 32 * m][k4 * 4]);
                    acc[0][m] = dot4(a0, hv, acc[0][m]);
                    acc[1][m] = dot4(a1, hv, acc[1][m]);
                }
            }

            #pragma unroll
            for (int si = 0; si < 2; si++) {
                float* sh = Shat + (size_t)(b * kN + s0 + 2 * w + si) * kN + tt * 128;
                #pragma unroll
                for (int m = 0; m < 4; m++) sh[32 * m + lane] = acc[si][m];
            }
        }
    }
    grid_bar();

    // ======== SM0: softmax(Shat) -> outS0 (= S_0 output AND step-0 S) ======
    softmax_rows(Shat, outS0, gw, lane);
    grid_bar();

    // ======== consensus steps ========
    #pragma unroll 1
    for (int step = 0; step < 2; step++) {
        const float* Ssrc = step ? Snorm : outS0;
        const float* rsk  = r_all + (size_t)step * SZ_NTR;
        const float* ask  = asbuf + (size_t)step * SZ_NTR;

        // ---- A: zero agg32t + rt = S^T @ r_s (256 units) ----
        {
            float4 zz = make_float4(0.f, 0.f, 0.f, 0.f);
            for (int i = bk * NTHR + tid; i < 32768; i += TOTT)
                reinterpret_cast<float4*>(agg32t)[i] = zz;
        }
        if (bk < 256) {
            int b = bk >> 5;
            int t0 = (bk & 31) * 16;
            const float* Sb = Ssrc + (size_t)b * kN * kN;
            const float* Rb = rsk + (size_t)b * kN * kR;
            int t_ = tid & 15, rp = tid >> 4;

            float acc0 = 0.f, acc1 = 0.f;
            #pragma unroll 1
            for (int ks = 0; ks < 8; ks++) {
                __syncthreads();
                {
                    int s = tid >> 2, t4 = tid & 3;
                    float4 v = *reinterpret_cast<const float4*>(
                        &Sb[(size_t)(ks * 64 + s) * kN + t0 + t4 * 4]);
                    sm.a.St[t4 * 4 + 0][s] = v.x;
                    sm.a.St[t4 * 4 + 1][s] = v.y;
                    sm.a.St[t4 * 4 + 2][s] = v.z;
                    sm.a.St[t4 * 4 + 3][s] = v.w;
                }
                #pragma unroll
                for (int i = tid; i < 512; i += NTHR) {
                    int s = i >> 3, r4 = i & 7;
                    float4 v = *reinterpret_cast<const float4*>(
                        &Rb[(size_t)(ks * 64 + s) * kR + r4 * 4]);
                    sm.a.Rt[r4 * 4 + 0][s] = v.x;
                    sm.a.Rt[r4 * 4 + 1][s] = v.y;
                    sm.a.Rt[r4 * 4 + 2][s] = v.z;
                    sm.a.Rt[r4 * 4 + 3][s] = v.w;
                }
                __syncthreads();
                #pragma unroll 4
                for (int k4 = 0; k4 < 16; k4++) {
                    float4 sv = *reinterpret_cast<const float4*>(&sm.a.St[t_][k4 * 4]);
                    float4 ra = *reinterpret_cast<const float4*>(&sm.a.Rt[2 * rp][k4 * 4]);
                    float4 rb = *reinterpret_cast<const float4*>(&sm.a.Rt[2 * rp + 1][k4 * 4]);
                    acc0 = dot4(sv, ra, acc0);
                    acc1 = dot4(sv, rb, acc1);
                }
            }
            float* rt0 = rtbuf + ((size_t)b * kN + t0 + t_) * kR + 2 * rp;
            *reinterpret_cast<float2*>(rt0) = make_float2(acc0, acc1);
        }
        grid_bar();

        // ---- B: scatter rt over t-graph edges ----
        #pragma unroll 1
        for (int gid = bk * NTHR + tid; gid < kE * 8; gid += TOTT) {
            int e = gid >> 3, c = gid & 7;
            int s = eit[e], d = eit[kE + e];
            float wgt = eat[e];
            float4 v = *reinterpret_cast<const float4*>(rtbuf + (size_t)s * 32 + c * 4);
            red4(agg32t + (size_t)d * 32 + c * 4, v, wgt);
        }
        grid_bar();

        // ---- C: psi2(rt, agg) @ Wm1 -> btbuf (256 units) ----
        if (bk < 256) {
            psi2_body<2>(sm.p, bk * 16, rtbuf, agg32t, W2_root, W2_nbr, b2, Wm1,
                         nullptr, btbuf, 0);
        }
        grid_bar();

        // ---- D: mlp + S_hat add, (b, s-tile, t-half) units ----
        #pragma unroll 1
        for (int u = bk; u < 512; u += NBLK) {
            int b  = u >> 6;
            int s0 = ((u >> 1) & 31) * 16;
            int th = u & 1;
            float bm2v = bm2[0];

            __syncthreads();
            if (tid < 32) sm.d.w2[tid] = Wm2[tid];
            const float4* Ab4 = reinterpret_cast<const float4*>(ask + ((size_t)b * kN + s0) * kR);
            for (int i = tid; i < 128; i += NTHR)
                *reinterpret_cast<float4*>(&sm.d.Asm[i >> 3][(i & 7) * 4]) = Ab4[i];

            #pragma unroll 1
            for (int tt2 = 0; tt2 < 2; tt2++) {
                int tt = th * 2 + tt2;
                __syncthreads();
                const float4* Bb4 = reinterpret_cast<const float4*>(btbuf + ((size_t)b * kN + tt * 128) * kR);
                for (int i = tid; i < 1024; i += NTHR)
                    *reinterpret_cast<float4*>(&sm.d.Bsm[i >> 3][(i & 7) * 4]) = Bb4[i];
                __syncthreads();

                float acc[2][4];
                #pragma unroll
                for (int i = 0; i < 2; i++)
                    #pragma unroll
                    for (int m = 0; m < 4; m++) acc[i][m] = 0.f;

                #pragma unroll 2
                for (int r4 = 0; r4 < 8; r4++) {
                    float4 ww = *reinterpret_cast<const float4*>(&sm.d.w2[r4 * 4]);
                    float4 a0 = *reinterpret_cast<const float4*>(&sm.d.Asm[2 * w][r4 * 4]);
                    float4 a1 = *reinterpret_cast<const float4*>(&sm.d.Asm[2 * w + 1][r4 * 4]);
                    #pragma unroll
                    for (int m = 0; m < 4; m++) {
                        float4 bv = *reinterpret_cast<const float4*>(&sm.d.Bsm[lane + 32 * m][r4 * 4]);
                        float d;
                        d = fmaxf(a0.x - bv.x, 0.f); acc[0][m] = fmaf(d, ww.x, acc[0][m]);
                        d = fmaxf(a0.y - bv.y, 0.f); acc[0][m] = fmaf(d, ww.y, acc[0][m]);
                        d = fmaxf(a0.z - bv.z, 0.f); acc[0][m] = fmaf(d, ww.z, acc[0][m]);
                        d = fmaxf(a0.w - bv.w, 0.f); acc[0][m] = fmaf(d, ww.w, acc[0][m]);
                        d = fmaxf(a1.x - bv.x, 0.f); acc[1][m] = fmaf(d, ww.x, acc[1][m]);
                        d = fmaxf(a1.y - bv.y, 0.f); acc[1][m] = fmaf(d, ww.y, acc[1][m]);
                        d = fmaxf(a1.z - bv.z, 0.f); acc[1][m] = fmaf(d, ww.z, acc[1][m]);
                        d = fmaxf(a1.w - bv.w, 0.f); acc[1][m] = fmaf(d, ww.w, acc[1][m]);
                    }
                }

                #pragma unroll
                for (int si = 0; si < 2; si++) {
                    float* sh = Shat + (size_t)(b * kN + s0 + 2 * w + si) * kN + tt * 128;
                    #pragma unroll
                    for (int m = 0; m < 4; m++) {
                        int t = 32 * m + lane;
                        sh[t] = sh[t] + acc[si][m] + bm2v;   // raw updated S_hat
                    }
                }
            }
        }
        grid_bar();

        // ---- SM: softmax(updated Shat) -> Snorm (step0) / outSL (step1) ----
        softmax_rows(Shat, step ? outSL : Snorm, gw, lane);
        if (step == 0) grid_bar();
    }
}

// ---------------------------------------------------------------------------
// Host launch (ONE kernel)
// ---------------------------------------------------------------------------
extern "C" void kernel_launch(void* const* d_in, const int* in_sizes, int n_in,
                              void* d_out, int out_size)
{
    (void)in_sizes; (void)n_in; (void)out_size;
    const float* x_s     = (const float*)d_in[0];
    const int*   ei_s    = (const int*)  d_in[1];
    const float* ea_s    = (const float*)d_in[2];
    const float* x_t     = (const float*)d_in[4];
    const int*   ei_t    = (const int*)  d_in[5];
    const float* ea_t    = (const float*)d_in[6];
    const float* r_all   = (const float*)d_in[8];
    const float* W1_root = (const float*)d_in[9];
    const float* W1_nbr  = (const float*)d_in[10];
    const float* b1      = (const float*)d_in[11];
    const float* W2_root = (const float*)d_in[12];
    const float* W2_nbr  = (const float*)d_in[13];
    const float* b2      = (const float*)d_in[14];
    const float* Wm1     = (const float*)d_in[15];
    const float* bm1     = (const float*)d_in[16];
    const float* Wm2     = (const float*)d_in[17];
    const float* bm2     = (const float*)d_in[18];

    float* outS0 = (float*)d_out;
    float* outSL = outS0 + SZ_S;

    mega_kernel<<<NBLK, NTHR>>>(x_s, x_t, ei_s, ea_s, ei_t, ea_t, r_all,
                                W1_root, W1_nbr, b1, W2_root, W2_nbr, b2,
                                Wm1, bm1, Wm2, bm2, outS0, outSL);
}

// round 11
// speedup vs baseline: 1.0604x; 1.0604x over previous
#include <cuda_runtime.h>
#include <cstdint>

// ---------------------------------------------------------------------------
// Problem constants
// ---------------------------------------------------------------------------
constexpr int kB   = 8;
constexpr int kN   = 512;
constexpr int kE   = 65536;
constexpr int kNT  = kB * kN;      // 4096
constexpr int kDH  = 64;
constexpr int kR   = 32;

constexpr size_t SZ_NTDH = (size_t)kNT * kDH;     // 262144
constexpr size_t SZ_NTR  = (size_t)kNT * kR;      // 131072
constexpr size_t SZ_S    = (size_t)kB * kN * kN;  // 2097152

constexpr size_t OFF_AGG64S = 0;
constexpr size_t OFF_AGG64T = OFF_AGG64S + SZ_NTDH;
constexpr size_t OFF_AGG32S = OFF_AGG64T + SZ_NTDH;   // 2 slots (steps 0,1)
constexpr size_t OFF_AGG32T = OFF_AGG32S + 2 * SZ_NTR;
constexpr size_t OFF_YS     = OFF_AGG32T + SZ_NTR;
constexpr size_t OFF_YT     = OFF_YS     + SZ_NTDH;
constexpr size_t OFF_HS     = OFF_YT     + SZ_NTDH;
constexpr size_t OFF_HT     = OFF_HS     + SZ_NTDH;
constexpr size_t OFF_SHAT   = OFF_HT     + SZ_NTDH;
constexpr size_t OFF_SNORM  = OFF_SHAT   + SZ_S;
constexpr size_t OFF_RT     = OFF_SNORM  + SZ_S;
constexpr size_t OFF_AS     = OFF_RT     + SZ_NTR;    // 2 steps
constexpr size_t OFF_BT     = OFF_AS     + 2 * SZ_NTR;
constexpr size_t SCRATCH_TOTAL = OFF_BT + SZ_NTR;

__device__ float g_scratch[SCRATCH_TOTAL];

constexpr int NBLK = 256;
constexpr int NTHR = 256;
constexpr int TOTT = NBLK * NTHR;         // 65536 threads
constexpr int NWARP = NBLK * 8;           // 2048 warps

// Ticket grid barrier (monotonic counter: safe across graph replays)
__device__ unsigned int g_bar = 0;

__device__ __forceinline__ void grid_bar() {
    __syncthreads();
    __threadfence();
    if (threadIdx.x == 0) {
        unsigned old = atomicAdd(&g_bar, 1u);
        unsigned target = (old / NBLK + 1u) * NBLK;
        while (*(volatile unsigned*)&g_bar < target) { }
    }
    __syncthreads();
    __threadfence();
}

__device__ __forceinline__ void red4(float* p, float4 v, float w) {
    asm volatile("red.global.add.v4.f32 [%0], {%1,%2,%3,%4};"
                 :: "l"(p), "f"(v.x * w), "f"(v.y * w), "f"(v.z * w), "f"(v.w * w)
                 : "memory");
}

// ---- packed f32x2 helpers (FFMA2 via PTX; ptxas will not emit it from C++) --
__device__ __forceinline__ void lds_v2u64(uint64_t& a, uint64_t& b, const void* p) {
    uint32_t s = (uint32_t)__cvta_generic_to_shared(p);
    asm volatile("ld.shared.v2.b64 {%0, %1}, [%2];" : "=l"(a), "=l"(b) : "r"(s));
}
__device__ __forceinline__ void ffma2(uint64_t& d, uint64_t a, uint64_t b) {
    asm volatile("fma.rn.f32x2 %0, %1, %2, %3;" : "=l"(d) : "l"(a), "l"(b), "l"(d));
}
__device__ __forceinline__ float unpack_add(uint64_t v) {
    float lo, hi;
    asm("mov.b64 {%0, %1}, %2;" : "=f"(lo), "=f"(hi) : "l"(v));
    return lo + hi;
}

// ---------------------------------------------------------------------------
// Shared memory layouts (union, 16B-aligned; row pads (68,36) keep 16B align)
// ---------------------------------------------------------------------------
struct RootSm { float As[16][128]; };                               // 8 KB
struct Psi2Sm {                                                     // ~25 KB
    float rsm[8][4][33];
    float gsm[8][4][33];
    float osm[8][4][33];
    float wr[32 * 33];
    float wn[32 * 33];
    float wm[32 * 33];
};
struct GemmSm { float hsS[16][68]; float htS[128][68]; };           // 38.3 KB
struct RtSm   { float St[16][68];  float Rt[32][68]; };             // 12.8 KB
struct MlpSm  { float Bsm[128][36]; float Asm[16][36]; float w2[32]; }; // 20.4 KB

union __align__(16) MegaSm {
    RootSm r; Psi2Sm p; GemmSm g; RtSm a; MlpSm d;
};

// ---------------------------------------------------------------------------
// psi_2 + Wm1 body (weights + operands staged in smem):
//   o = relu( r @ W2_root + agg @ W2_nbr + b2 ); out = o @ Wm1 (+ bm1)
// ---------------------------------------------------------------------------
template<int RPW>
__device__ __forceinline__ void psi2_body(
    Psi2Sm& sm, int row_base,
    const float* __restrict__ r, const float* __restrict__ agg,
    const float* __restrict__ W2_root, const float* __restrict__ W2_nbr,
    const float* __restrict__ b2, const float* __restrict__ Wm1,
    const float* __restrict__ bm1, float* __restrict__ out, int hasBm1)
{
    int tid = threadIdx.x;
    for (int i = tid; i < 1024; i += NTHR) {
        int k = i >> 5, c = i & 31;
        sm.wr[k * 33 + c] = W2_root[i];
        sm.wn[k * 33 + c] = W2_nbr[i];
        sm.wm[k * 33 + c] = Wm1[i];
    }
    int warp = tid >> 5, lane = tid & 31;
    int row0 = row_base + warp * RPW;

    #pragma unroll
    for (int rr = 0; rr < RPW; rr++) {
        sm.rsm[warp][rr][lane] = r[(size_t)(row0 + rr) * 32 + lane];
        sm.gsm[warp][rr][lane] = agg[(size_t)(row0 + rr) * 32 + lane];
    }
    __syncthreads();

    float o[RPW];
    float bv = b2[lane];
    #pragma unroll
    for (int rr = 0; rr < RPW; rr++) o[rr] = bv;
    #pragma unroll 8
    for (int k = 0; k < 32; k++) {
        float wr = sm.wr[k * 33 + lane];
        float wn = sm.wn[k * 33 + lane];
        #pragma unroll
        for (int rr = 0; rr < RPW; rr++) {
            o[rr] = fmaf(sm.rsm[warp][rr][k], wr, o[rr]);
            o[rr] = fmaf(sm.gsm[warp][rr][k], wn, o[rr]);
        }
    }
    #pragma unroll
    for (int rr = 0; rr < RPW; rr++) sm.osm[warp][rr][lane] = fmaxf(o[rr], 0.f);
    __syncwarp();

    float a[RPW];
    float b0 = hasBm1 ? bm1[lane] : 0.f;
    #pragma unroll
    for (int rr = 0; rr < RPW; rr++) a[rr] = b0;
    #pragma unroll 8
    for (int k = 0; k < 32; k++) {
        float w = sm.wm[k * 33 + lane];
        #pragma unroll
        for (int rr = 0; rr < RPW; rr++) a[rr] = fmaf(sm.osm[warp][rr][k], w, a[rr]);
    }
    #pragma unroll
    for (int rr = 0; rr < RPW; rr++) out[(size_t)(row0 + rr) * 32 + lane] = a[rr];
}

// ---------------------------------------------------------------------------
// proj/root GEMM tile: 16 rows x 64 cols, K=128, float4 A reads.
// ---------------------------------------------------------------------------
template<bool RELU, bool HASBIAS, bool HASADD>
__device__ __forceinline__ void rowgemm_tile(
    RootSm& sm, int row0,
    const float* __restrict__ A, const float* __restrict__ W,
    const float* __restrict__ bias, const float* __restrict__ add,
    float* __restrict__ out)
{
    int tid = threadIdx.x;
    const float4* A4 = reinterpret_cast<const float4*>(A + (size_t)row0 * 128);
    __syncthreads();
    for (int i = tid; i < 512; i += NTHR)
        *reinterpret_cast<float4*>(&sm.As[i >> 5][(i & 31) * 4]) = A4[i];
    __syncthreads();

    int j = tid & 63, g = tid >> 6;
    float acc[4];
    float bv = HASBIAS ? bias[j] : 0.f;
    #pragma unroll
    for (int rr = 0; rr < 4; rr++) acc[rr] = bv;

    #pragma unroll 4
    for (int k4 = 0; k4 < 32; k4++) {
        float w0 = __ldg(&W[(k4 * 4 + 0) * 64 + j]);
        float w1 = __ldg(&W[(k4 * 4 + 1) * 64 + j]);
        float w2 = __ldg(&W[(k4 * 4 + 2) * 64 + j]);
        float w3 = __ldg(&W[(k4 * 4 + 3) * 64 + j]);
        #pragma unroll
        for (int rr = 0; rr < 4; rr++) {
            float4 av = *reinterpret_cast<const float4*>(&sm.As[g * 4 + rr][k4 * 4]);
            acc[rr] = fmaf(av.x, w0, fmaf(av.y, w1, fmaf(av.z, w2, fmaf(av.w, w3, acc[rr]))));
        }
    }
    #pragma unroll
    for (int rr = 0; rr < 4; rr++) {
        size_t idx = (size_t)(row0 + g * 4 + rr) * 64 + j;
        float v = acc[rr];
        if (HASADD) v += add[idx];
        if (RELU)   v = fmaxf(v, 0.f);
        out[idx] = v;
    }
}

// ---------------------------------------------------------------------------
// Row softmax pass: warp per 2 rows, fully in registers.
// ---------------------------------------------------------------------------
__device__ __forceinline__ void softmax_rows(
    const float* __restrict__ src, float* __restrict__ dst, int gw, int lane)
{
    #pragma unroll 1
    for (int rr = 0; rr < 2; rr++) {
        int row = gw * 2 + rr;
        const float4* p = reinterpret_cast<const float4*>(src + (size_t)row * kN);
        float v[16];
        #pragma unroll
        for (int q = 0; q < 4; q++) {
            float4 t = p[lane + 32 * q];
            v[4 * q] = t.x; v[4 * q + 1] = t.y; v[4 * q + 2] = t.z; v[4 * q + 3] = t.w;
        }
        float m = v[0];
        #pragma unroll
        for (int j = 1; j < 16; j++) m = fmaxf(m, v[j]);
        #pragma unroll
        for (int o = 16; o > 0; o >>= 1) m = fmaxf(m, __shfl_xor_sync(0xffffffffu, m, o));
        float s = 0.f;
        #pragma unroll
        for (int j = 0; j < 16; j++) { v[j] = __expf(v[j] - m); s += v[j]; }
        #pragma unroll
        for (int o = 16; o > 0; o >>= 1) s += __shfl_xor_sync(0xffffffffu, s, o);
        float inv = 1.f / s;
        float4* o4 = reinterpret_cast<float4*>(dst + (size_t)row * kN);
        #pragma unroll
        for (int q = 0; q < 4; q++)
            o4[lane + 32 * q] = make_float4(v[4 * q] * inv, v[4 * q + 1] * inv,
                                            v[4 * q + 2] * inv, v[4 * q + 3] * inv);
    }
}

// ---------------------------------------------------------------------------
// THE kernel: 256 blocks x 256 threads, __launch_bounds__(256, 3).
// P3 / rt inner loops use packed fma.rn.f32x2 (k-dimension pairs).
// ---------------------------------------------------------------------------
__global__ __launch_bounds__(256, 3) void mega_kernel(
    const float* __restrict__ x_s, const float* __restrict__ x_t,
    const int* __restrict__ eis, const float* __restrict__ eas,
    const int* __restrict__ eit, const float* __restrict__ eat,
    const float* __restrict__ r_all,
    const float* __restrict__ W1_root, const float* __restrict__ W1_nbr,
    const float* __restrict__ b1,
    const float* __restrict__ W2_root, const float* __restrict__ W2_nbr,
    const float* __restrict__ b2,
    const float* __restrict__ Wm1, const float* __restrict__ bm1,
    const float* __restrict__ Wm2, const float* __restrict__ bm2,
    float* __restrict__ outS0, float* __restrict__ outSL)
{
    __shared__ MegaSm sm;

    int tid = threadIdx.x;
    int bk = blockIdx.x;
    int w = tid >> 5, lane = tid & 31;
    int gw = bk * 8 + w;   // global warp id 0..2047

    float* agg64s = g_scratch + OFF_AGG64S;
    float* agg64t = g_scratch + OFF_AGG64T;
    float* agg32s = g_scratch + OFF_AGG32S;
    float* agg32t = g_scratch + OFF_AGG32T;
    float* ys     = g_scratch + OFF_YS;
    float* yt     = g_scratch + OFF_YT;
    float* hs     = g_scratch + OFF_HS;
    float* ht     = g_scratch + OFF_HT;
    float* Shat   = g_scratch + OFF_SHAT;
    float* Snorm  = g_scratch + OFF_SNORM;
    float* rtbuf  = g_scratch + OFF_RT;
    float* asbuf  = g_scratch + OFF_AS;
    float* btbuf  = g_scratch + OFF_BT;

    // ======== P0: zero atomic buffers + projection y = x @ W1_nbr ========
    {
        float4* z4 = reinterpret_cast<float4*>(agg64s);
        int base = bk * NTHR + tid;
        float4 zz = make_float4(0.f, 0.f, 0.f, 0.f);
        z4[base] = zz; z4[base + 65536] = zz; z4[base + 131072] = zz;
    }
    #pragma unroll 1
    for (int it = 0; it < 2; it++) {
        int tl = bk + NBLK * it;
        int y = tl >> 8;
        rowgemm_tile<false, false, false>(sm.r, (tl & 255) * 16,
                                          y ? x_t : x_s, W1_nbr, nullptr, nullptr,
                                          y ? yt : ys);
    }
    grid_bar();

    // ======== P1: input-side scatters (atomics) ========
    #pragma unroll 1
    for (int graph = 0; graph < 2; graph++) {
        const float* yy  = graph ? yt : ys;
        const int*   ei  = graph ? eit : eis;
        const float* ea  = graph ? eat : eas;
        float*       agg = graph ? agg64t : agg64s;
        #pragma unroll 2
        for (int it = 0; it < 16; it++) {
            int gid = it * TOTT + bk * NTHR + tid;
            int e = gid >> 4, c = gid & 15;
            int s = ei[e], d = ei[kE + e];
            float wgt = ea[e];
            float4 v = *reinterpret_cast<const float4*>(yy + (size_t)s * 64 + c * 4);
            red4(agg + (size_t)d * 64 + c * 4, v, wgt);
        }
    }
    // raw-r s-graph scatter: BOTH steps per edge visit (index loaded once)
    #pragma unroll 2
    for (int it = 0; it < 8; it++) {
        int gid = it * TOTT + bk * NTHR + tid;
        int e = gid >> 3, c = gid & 7;
        int s = eis[e], d = eis[kE + e];
        float wgt = eas[e];
        float4 v0 = *reinterpret_cast<const float4*>(r_all + (size_t)s * 32 + c * 4);
        red4(agg32s + (size_t)d * 32 + c * 4, v0, wgt);
        float4 v1 = *reinterpret_cast<const float4*>(r_all + SZ_NTR + (size_t)s * 32 + c * 4);
        red4(agg32s + SZ_NTR + (size_t)d * 32 + c * 4, v1, wgt);
    }
    grid_bar();

    // ======== P2: root GEMM + a_s psi2 (both steps) ========
    #pragma unroll 1
    for (int it = 0; it < 2; it++) {
        int tl = bk + NBLK * it;
        int y = tl >> 8;
        rowgemm_tile<true, true, true>(sm.r, (tl & 255) * 16,
                                       y ? x_t : x_s, W1_root, b1,
                                       y ? agg64t : agg64s,
                                       y ? ht : hs);
    }
    __syncthreads();
    {
        int step = bk >> 7;
        psi2_body<4>(sm.p, (bk & 127) * 32,
                     r_all + (size_t)step * SZ_NTR, agg32s + (size_t)step * SZ_NTR,
                     W2_root, W2_nbr, b2, Wm1, bm1,
                     asbuf + (size_t)step * SZ_NTR, 1);
    }
    grid_bar();

    // ======== P3: S_hat0 = h_s @ h_t^T, streaming, packed f32x2 ========
    {
        int b  = bk >> 5;
        int s0 = (bk & 31) * 16;

        const float4* hsb4 = reinterpret_cast<const float4*>(hs + ((size_t)b * kN + s0) * kDH);
        for (int i = tid; i < 256; i += NTHR)
            *reinterpret_cast<float4*>(&sm.g.hsS[i >> 4][(i & 15) * 4]) = hsb4[i];

        #pragma unroll 1
        for (int tt = 0; tt < 4; tt++) {
            __syncthreads();
            const float4* htb4 = reinterpret_cast<const float4*>(ht + ((size_t)b * kN + tt * 128) * kDH);
            for (int i = tid; i < 2048; i += NTHR)
                *reinterpret_cast<float4*>(&sm.g.htS[i >> 4][(i & 15) * 4]) = htb4[i];
            __syncthreads();

            uint64_t acc2[2][4];
            #pragma unroll
            for (int i = 0; i < 2; i++)
                #pragma unroll
                for (int m = 0; m < 4; m++) acc2[i][m] = 0ull;

            #pragma unroll 4
            for (int k4 = 0; k4 < 16; k4++) {
                uint64_t a00, a01, a10, a11;
                lds_v2u64(a00, a01, &sm.g.hsS[2 * w][k4 * 4]);
                lds_v2u64(a10, a11, &sm.g.hsS[2 * w + 1][k4 * 4]);
                #pragma unroll
                for (int m = 0; m < 4; m++) {
                    uint64_t h0, h1;
                    lds_v2u64(h0, h1, &sm.g.htS[lane + 32 * m][k4 * 4]);
                    ffma2(acc2[0][m], a00, h0);
                    ffma2(acc2[0][m], a01, h1);
                    ffma2(acc2[1][m], a10, h0);
                    ffma2(acc2[1][m], a11, h1);
                }
            }

            #pragma unroll
            for (int si = 0; si < 2; si++) {
                float* sh = Shat + (size_t)(b * kN + s0 + 2 * w + si) * kN + tt * 128;
                #pragma unroll
                for (int m = 0; m < 4; m++) sh[32 * m + lane] = unpack_add(acc2[si][m]);
            }
        }
    }
    grid_bar();

    // ======== SM0: softmax(Shat) -> outS0 (= S_0 output AND step-0 S) ======
    softmax_rows(Shat, outS0, gw, lane);
    grid_bar();

    // ======== consensus steps ========
    #pragma unroll 1
    for (int step = 0; step < 2; step++) {
        const float* Ssrc = step ? Snorm : outS0;
        const float* rsk  = r_all + (size_t)step * SZ_NTR;
        const float* ask  = asbuf + (size_t)step * SZ_NTR;

        // ---- A: zero agg32t + rt = S^T @ r_s (packed f32x2) ----
        {
            int gid = bk * NTHR + tid;
            reinterpret_cast<float4*>(agg32t)[gid & 32767] =
                make_float4(0.f, 0.f, 0.f, 0.f);
        }
        {
            int b = bk >> 5;
            int t0 = (bk & 31) * 16;
            const float* Sb = Ssrc + (size_t)b * kN * kN;
            const float* Rb = rsk + (size_t)b * kN * kR;
            int t_ = tid & 15, rp = tid >> 4;

            uint64_t accA = 0ull, accB = 0ull;
            #pragma unroll 1
            for (int ks = 0; ks < 8; ks++) {
                __syncthreads();
                {
                    int s = tid >> 2, t4 = tid & 3;
                    float4 v = *reinterpret_cast<const float4*>(
                        &Sb[(size_t)(ks * 64 + s) * kN + t0 + t4 * 4]);
                    sm.a.St[t4 * 4 + 0][s] = v.x;
                    sm.a.St[t4 * 4 + 1][s] = v.y;
                    sm.a.St[t4 * 4 + 2][s] = v.z;
                    sm.a.St[t4 * 4 + 3][s] = v.w;
                }
                #pragma unroll
                for (int i = tid; i < 512; i += NTHR) {
                    int s = i >> 3, r4 = i & 7;
                    float4 v = *reinterpret_cast<const float4*>(
                        &Rb[(size_t)(ks * 64 + s) * kR + r4 * 4]);
                    sm.a.Rt[r4 * 4 + 0][s] = v.x;
                    sm.a.Rt[r4 * 4 + 1][s] = v.y;
                    sm.a.Rt[r4 * 4 + 2][s] = v.z;
                    sm.a.Rt[r4 * 4 + 3][s] = v.w;
                }
                __syncthreads();
                #pragma unroll 4
                for (int k4 = 0; k4 < 16; k4++) {
                    uint64_t s0p, s1p, ra0, ra1, rb0, rb1;
                    lds_v2u64(s0p, s1p, &sm.a.St[t_][k4 * 4]);
                    lds_v2u64(ra0, ra1, &sm.a.Rt[2 * rp][k4 * 4]);
                    lds_v2u64(rb0, rb1, &sm.a.Rt[2 * rp + 1][k4 * 4]);
                    ffma2(accA, s0p, ra0);
                    ffma2(accA, s1p, ra1);
                    ffma2(accB, s0p, rb0);
                    ffma2(accB, s1p, rb1);
                }
            }
            float* rt0 = rtbuf + ((size_t)b * kN + t0 + t_) * kR + 2 * rp;
            *reinterpret_cast<float2*>(rt0) =
                make_float2(unpack_add(accA), unpack_add(accB));
        }
        grid_bar();

        // ---- B: scatter rt over t-graph edges ----
        #pragma unroll 2
        for (int it = 0; it < 8; it++) {
            int gid = it * TOTT + bk * NTHR + tid;
            int e = gid >> 3, c = gid & 7;
            int s = eit[e], d = eit[kE + e];
            float wgt = eat[e];
            float4 v = *reinterpret_cast<const float4*>(rtbuf + (size_t)s * 32 + c * 4);
            red4(agg32t + (size_t)d * 32 + c * 4, v, wgt);
        }
        grid_bar();

        // ---- C: psi2(rt, agg) @ Wm1 -> btbuf ----
        psi2_body<2>(sm.p, bk * 16, rtbuf, agg32t, W2_root, W2_nbr, b2, Wm1,
                     nullptr, btbuf, 0);
        grid_bar();

        // ---- D: mlp + S_hat add, streaming raw writes into Shat ----
        {
            int b  = bk >> 5;
            int s0 = (bk & 31) * 16;
            float bm2v = bm2[0];

            if (tid < 32) sm.d.w2[tid] = Wm2[tid];
            const float4* Ab4 = reinterpret_cast<const float4*>(ask + ((size_t)b * kN + s0) * kR);
            for (int i = tid; i < 128; i += NTHR)
                *reinterpret_cast<float4*>(&sm.d.Asm[i >> 3][(i & 7) * 4]) = Ab4[i];

            #pragma unroll 1
            for (int tt = 0; tt < 4; tt++) {
                __syncthreads();
                const float4* Bb4 = reinterpret_cast<const float4*>(btbuf + ((size_t)b * kN + tt * 128) * kR);
                for (int i = tid; i < 1024; i += NTHR)
                    *reinterpret_cast<float4*>(&sm.d.Bsm[i >> 3][(i & 7) * 4]) = Bb4[i];
                __syncthreads();

                float acc[2][4];
                #pragma unroll
                for (int i = 0; i < 2; i++)
                    #pragma unroll
                    for (int m = 0; m < 4; m++) acc[i][m] = 0.f;

                #pragma unroll 2
                for (int r4 = 0; r4 < 8; r4++) {
                    float4 ww = *reinterpret_cast<const float4*>(&sm.d.w2[r4 * 4]);
                    float4 a0 = *reinterpret_cast<const float4*>(&sm.d.Asm[2 * w][r4 * 4]);
                    float4 a1 = *reinterpret_cast<const float4*>(&sm.d.Asm[2 * w + 1][r4 * 4]);
                    #pragma unroll
                    for (int m = 0; m < 4; m++) {
                        float4 bv = *reinterpret_cast<const float4*>(&sm.d.Bsm[lane + 32 * m][r4 * 4]);
                        float d;
                        d = fmaxf(a0.x - bv.x, 0.f); acc[0][m] = fmaf(d, ww.x, acc[0][m]);
                        d = fmaxf(a0.y - bv.y, 0.f); acc[0][m] = fmaf(d, ww.y, acc[0][m]);
                        d = fmaxf(a0.z - bv.z, 0.f); acc[0][m] = fmaf(d, ww.z, acc[0][m]);
                        d = fmaxf(a0.w - bv.w, 0.f); acc[0][m] = fmaf(d, ww.w, acc[0][m]);
                        d = fmaxf(a1.x - bv.x, 0.f); acc[1][m] = fmaf(d, ww.x, acc[1][m]);
                        d = fmaxf(a1.y - bv.y, 0.f); acc[1][m] = fmaf(d, ww.y, acc[1][m]);
                        d = fmaxf(a1.z - bv.z, 0.f); acc[1][m] = fmaf(d, ww.z, acc[1][m]);
                        d = fmaxf(a1.w - bv.w, 0.f); acc[1][m] = fmaf(d, ww.w, acc[1][m]);
                    }
                }

                #pragma unroll
                for (int si = 0; si < 2; si++) {
                    float* sh = Shat + (size_t)(b * kN + s0 + 2 * w + si) * kN + tt * 128;
                    #pragma unroll
                    for (int m = 0; m < 4; m++) {
                        int t = 32 * m + lane;
                        sh[t] = sh[t] + acc[si][m] + bm2v;   // raw updated S_hat
                    }
                }
            }
        }
        grid_bar();

        // ---- SM: softmax(updated Shat) -> Snorm (step0) / outSL (step1) ----
        softmax_rows(Shat, step ? outSL : Snorm, gw, lane);
        if (step == 0) grid_bar();
    }
}

// ---------------------------------------------------------------------------
// Host launch (ONE kernel)
// ---------------------------------------------------------------------------
extern "C" void kernel_launch(void* const* d_in, const int* in_sizes, int n_in,
                              void* d_out, int out_size)
{
    (void)in_sizes; (void)n_in; (void)out_size;
    const float* x_s     = (const float*)d_in[0];
    const int*   ei_s    = (const int*)  d_in[1];
    const float* ea_s    = (const float*)d_in[2];
    const float* x_t     = (const float*)d_in[4];
    const int*   ei_t    = (const int*)  d_in[5];
    const float* ea_t    = (const float*)d_in[6];
    const float* r_all   = (const float*)d_in[8];
    const float* W1_root = (const float*)d_in[9];
    const float* W1_nbr  = (const float*)d_in[10];
    const float* b1      = (const float*)d_in[11];
    const float* W2_root = (const float*)d_in[12];
    const float* W2_nbr  = (const float*)d_in[13];
    const float* b2      = (const float*)d_in[14];
    const float* Wm1     = (const float*)d_in[15];
    const float* bm1     = (const float*)d_in[16];
    const float* Wm2     = (const float*)d_in[17];
    const float* bm2     = (const float*)d_in[18];

    float* outS0 = (float*)d_out;
    float* outSL = outS0 + SZ_S;

    mega_kernel<<<NBLK, NTHR>>>(x_s, x_t, ei_s, ea_s, ei_t, ea_t, r_all,
                                W1_root, W1_nbr, b1, W2_root, W2_nbr, b2,
                                Wm1, bm1, Wm2, bm2, outS0, outSL);
}

// round 12
// speedup vs baseline: 1.1152x; 1.0517x over previous
#include <cuda_runtime.h>
#include <cstdint>

// ---------------------------------------------------------------------------
// Problem constants
// ---------------------------------------------------------------------------
constexpr int kB   = 8;
constexpr int kN   = 512;
constexpr int kE   = 65536;
constexpr int kNT  = kB * kN;      // 4096
constexpr int kDH  = 64;
constexpr int kR   = 32;

constexpr size_t SZ_NTDH = (size_t)kNT * kDH;     // 262144
constexpr size_t SZ_NTR  = (size_t)kNT * kR;      // 131072
constexpr size_t SZ_S    = (size_t)kB * kN * kN;  // 2097152

constexpr size_t OFF_AGG64S = 0;
constexpr size_t OFF_AGG64T = OFF_AGG64S + SZ_NTDH;
constexpr size_t OFF_AGG32S = OFF_AGG64T + SZ_NTDH;   // 2 slots (steps 0,1)
constexpr size_t OFF_AGG32T = OFF_AGG32S + 2 * SZ_NTR;
constexpr size_t OFF_YS     = OFF_AGG32T + SZ_NTR;
constexpr size_t OFF_YT     = OFF_YS     + SZ_NTDH;
constexpr size_t OFF_HS     = OFF_YT     + SZ_NTDH;
constexpr size_t OFF_HT     = OFF_HS     + SZ_NTDH;
constexpr size_t OFF_SHAT   = OFF_HT     + SZ_NTDH;
constexpr size_t OFF_SNORM  = OFF_SHAT   + SZ_S;
constexpr size_t OFF_RT     = OFF_SNORM  + SZ_S;
constexpr size_t OFF_AS     = OFF_RT     + SZ_NTR;    // 2 steps
constexpr size_t OFF_BT     = OFF_AS     + 2 * SZ_NTR;
constexpr size_t SCRATCH_TOTAL = OFF_BT + SZ_NTR;

__device__ float g_scratch[SCRATCH_TOTAL];

constexpr int NBLK = 256;
constexpr int NTHR = 256;
constexpr int TOTT = NBLK * NTHR;         // 65536 threads

// Ticket grid barrier (monotonic counter: safe across graph replays)
__device__ unsigned int g_bar = 0;

__device__ __forceinline__ void grid_bar() {
    __syncthreads();
    __threadfence();
    if (threadIdx.x == 0) {
        unsigned old = atomicAdd(&g_bar, 1u);
        unsigned target = (old / NBLK + 1u) * NBLK;
        while (*(volatile unsigned*)&g_bar < target) { }
    }
    __syncthreads();
    __threadfence();
}

__device__ __forceinline__ void red4(float* p, float4 v, float w) {
    asm volatile("red.global.add.v4.f32 [%0], {%1,%2,%3,%4};"
                 :: "l"(p), "f"(v.x * w), "f"(v.y * w), "f"(v.z * w), "f"(v.w * w)
                 : "memory");
}

// ---- packed f32x2 helpers (FFMA2 via PTX) ----------------------------------
__device__ __forceinline__ void lds_v2u64(uint64_t& a, uint64_t& b, const void* p) {
    uint32_t s = (uint32_t)__cvta_generic_to_shared(p);
    asm volatile("ld.shared.v2.b64 {%0, %1}, [%2];" : "=l"(a), "=l"(b) : "r"(s));
}
__device__ __forceinline__ void ffma2(uint64_t& d, uint64_t a, uint64_t b) {
    asm volatile("fma.rn.f32x2 %0, %1, %2, %3;" : "=l"(d) : "l"(a), "l"(b), "l"(d));
}
__device__ __forceinline__ float unpack_add(uint64_t v) {
    float lo, hi;
    asm("mov.b64 {%0, %1}, %2;" : "=f"(lo), "=f"(hi) : "l"(v));
    return lo + hi;
}

// ---------------------------------------------------------------------------
// Shared memory layouts (union, 16B-aligned; pads (68,36) keep 16B alignment
// and conflict-free float4 cross-row access: 272 % 128 = 16, 144 % 128 = 16)
// ---------------------------------------------------------------------------
struct RootSm { float As[16][128]; };                                // 8 KB
struct Psi2Sm {                                                      // ~25 KB
    float rsm[8][4][33];
    float gsm[8][4][33];
    float osm[8][4][33];
    float wr[32 * 33];
    float wn[32 * 33];
    float wm[32 * 33];
};
struct GemmSm { float hsS[32][68]; float htS[128][68]; };            // 43.5 KB
struct RtSm   { float St[16][68];  float Rt[32][68]; };              // 12.8 KB
struct MlpSm  { float Bsm[128][36]; float Asm[32][36]; float w2[32]; }; // 23 KB

union __align__(16) MegaSm {
    RootSm r; Psi2Sm p; GemmSm g; RtSm a; MlpSm d;
};

// ---------------------------------------------------------------------------
// psi_2 + Wm1 body (weights + operands staged in smem):
//   o = relu( r @ W2_root + agg @ W2_nbr + b2 ); out = o @ Wm1 (+ bm1)
// ---------------------------------------------------------------------------
template<int RPW>
__device__ __forceinline__ void psi2_body(
    Psi2Sm& sm, int row_base,
    const float* __restrict__ r, const float* __restrict__ agg,
    const float* __restrict__ W2_root, const float* __restrict__ W2_nbr,
    const float* __restrict__ b2, const float* __restrict__ Wm1,
    const float* __restrict__ bm1, float* __restrict__ out, int hasBm1)
{
    int tid = threadIdx.x;
    for (int i = tid; i < 1024; i += NTHR) {
        int k = i >> 5, c = i & 31;
        sm.wr[k * 33 + c] = W2_root[i];
        sm.wn[k * 33 + c] = W2_nbr[i];
        sm.wm[k * 33 + c] = Wm1[i];
    }
    int warp = tid >> 5, lane = tid & 31;
    int row0 = row_base + warp * RPW;

    #pragma unroll
    for (int rr = 0; rr < RPW; rr++) {
        sm.rsm[warp][rr][lane] = r[(size_t)(row0 + rr) * 32 + lane];
        sm.gsm[warp][rr][lane] = agg[(size_t)(row0 + rr) * 32 + lane];
    }
    __syncthreads();

    float o[RPW];
    float bv = b2[lane];
    #pragma unroll
    for (int rr = 0; rr < RPW; rr++) o[rr] = bv;
    #pragma unroll 8
    for (int k = 0; k < 32; k++) {
        float wr = sm.wr[k * 33 + lane];
        float wn = sm.wn[k * 33 + lane];
        #pragma unroll
        for (int rr = 0; rr < RPW; rr++) {
            o[rr] = fmaf(sm.rsm[warp][rr][k], wr, o[rr]);
            o[rr] = fmaf(sm.gsm[warp][rr][k], wn, o[rr]);
        }
    }
    #pragma unroll
    for (int rr = 0; rr < RPW; rr++) sm.osm[warp][rr][lane] = fmaxf(o[rr], 0.f);
    __syncwarp();

    float a[RPW];
    float b0 = hasBm1 ? bm1[lane] : 0.f;
    #pragma unroll
    for (int rr = 0; rr < RPW; rr++) a[rr] = b0;
    #pragma unroll 8
    for (int k = 0; k < 32; k++) {
        float w = sm.wm[k * 33 + lane];
        #pragma unroll
        for (int rr = 0; rr < RPW; rr++) a[rr] = fmaf(sm.osm[warp][rr][k], w, a[rr]);
    }
    #pragma unroll
    for (int rr = 0; rr < RPW; rr++) out[(size_t)(row0 + rr) * 32 + lane] = a[rr];
}

// ---------------------------------------------------------------------------
// proj/root GEMM tile: 16 rows x 64 cols, K=128, float4 A reads.
// ---------------------------------------------------------------------------
template<bool RELU, bool HASBIAS, bool HASADD>
__device__ __forceinline__ void rowgemm_tile(
    RootSm& sm, int row0,
    const float* __restrict__ A, const float* __restrict__ W,
    const float* __restrict__ bias, const float* __restrict__ add,
    float* __restrict__ out)
{
    int tid = threadIdx.x;
    const float4* A4 = reinterpret_cast<const float4*>(A + (size_t)row0 * 128);
    __syncthreads();
    for (int i = tid; i < 512; i += NTHR)
        *reinterpret_cast<float4*>(&sm.As[i >> 5][(i & 31) * 4]) = A4[i];
    __syncthreads();

    int j = tid & 63, g = tid >> 6;
    float acc[4];
    float bv = HASBIAS ? bias[j] : 0.f;
    #pragma unroll
    for (int rr = 0; rr < 4; rr++) acc[rr] = bv;

    #pragma unroll 4
    for (int k4 = 0; k4 < 32; k4++) {
        float w0 = __ldg(&W[(k4 * 4 + 0) * 64 + j]);
        float w1 = __ldg(&W[(k4 * 4 + 1) * 64 + j]);
        float w2 = __ldg(&W[(k4 * 4 + 2) * 64 + j]);
        float w3 = __ldg(&W[(k4 * 4 + 3) * 64 + j]);
        #pragma unroll
        for (int rr = 0; rr < 4; rr++) {
            float4 av = *reinterpret_cast<const float4*>(&sm.As[g * 4 + rr][k4 * 4]);
            acc[rr] = fmaf(av.x, w0, fmaf(av.y, w1, fmaf(av.z, w2, fmaf(av.w, w3, acc[rr]))));
        }
    }
    #pragma unroll
    for (int rr = 0; rr < 4; rr++) {
        size_t idx = (size_t)(row0 + g * 4 + rr) * 64 + j;
        float v = acc[rr];
        if (HASADD) v += add[idx];
        if (RELU)   v = fmaxf(v, 0.f);
        out[idx] = v;
    }
}

// ---------------------------------------------------------------------------
// Row softmax pass: warp per 2 rows, fully in registers.
// ---------------------------------------------------------------------------
__device__ __forceinline__ void softmax_rows(
    const float* __restrict__ src, float* __restrict__ dst, int gw, int lane)
{
    #pragma unroll 1
    for (int rr = 0; rr < 2; rr++) {
        int row = gw * 2 + rr;
        const float4* p = reinterpret_cast<const float4*>(src + (size_t)row * kN);
        float v[16];
        #pragma unroll
        for (int q = 0; q < 4; q++) {
            float4 t = p[lane + 32 * q];
            v[4 * q] = t.x; v[4 * q + 1] = t.y; v[4 * q + 2] = t.z; v[4 * q + 3] = t.w;
        }
        float m = v[0];
        #pragma unroll
        for (int j = 1; j < 16; j++) m = fmaxf(m, v[j]);
        #pragma unroll
        for (int o = 16; o > 0; o >>= 1) m = fmaxf(m, __shfl_xor_sync(0xffffffffu, m, o));
        float s = 0.f;
        #pragma unroll
        for (int j = 0; j < 16; j++) { v[j] = __expf(v[j] - m); s += v[j]; }
        #pragma unroll
        for (int o = 16; o > 0; o >>= 1) s += __shfl_xor_sync(0xffffffffu, s, o);
        float inv = 1.f / s;
        float4* o4 = reinterpret_cast<float4*>(dst + (size_t)row * kN);
        #pragma unroll
        for (int q = 0; q < 4; q++)
            o4[lane + 32 * q] = make_float4(v[4 * q] * inv, v[4 * q + 1] * inv,
                                            v[4 * q + 2] * inv, v[4 * q + 3] * inv);
    }
}

// ---------------------------------------------------------------------------
// THE kernel: 256 blocks x 256 threads, __launch_bounds__(256, 2).
// Heavy phases (P3, D): 32 s-rows/block, 4 rows/warp, unit = (b, s-tile, t-half)
// = exactly 256 units -> zero idle blocks, halved smem wavefronts per FMA.
// ---------------------------------------------------------------------------
__global__ __launch_bounds__(256, 2) void mega_kernel(
    const float* __restrict__ x_s, const float* __restrict__ x_t,
    const int* __restrict__ eis, const float* __restrict__ eas,
    const int* __restrict__ eit, const float* __restrict__ eat,
    const float* __restrict__ r_all,
    const float* __restrict__ W1_root, const float* __restrict__ W1_nbr,
    const float* __restrict__ b1,
    const float* __restrict__ W2_root, const float* __restrict__ W2_nbr,
    const float* __restrict__ b2,
    const float* __restrict__ Wm1, const float* __restrict__ bm1,
    const float* __restrict__ Wm2, const float* __restrict__ bm2,
    float* __restrict__ outS0, float* __restrict__ outSL)
{
    __shared__ MegaSm sm;

    int tid = threadIdx.x;
    int bk = blockIdx.x;
    int w = tid >> 5, lane = tid & 31;
    int gw = bk * 8 + w;   // global warp id 0..2047

    float* agg64s = g_scratch + OFF_AGG64S;
    float* agg64t = g_scratch + OFF_AGG64T;
    float* agg32s = g_scratch + OFF_AGG32S;
    float* agg32t = g_scratch + OFF_AGG32T;
    float* ys     = g_scratch + OFF_YS;
    float* yt     = g_scratch + OFF_YT;
    float* hs     = g_scratch + OFF_HS;
    float* ht     = g_scratch + OFF_HT;
    float* Shat   = g_scratch + OFF_SHAT;
    float* Snorm  = g_scratch + OFF_SNORM;
    float* rtbuf  = g_scratch + OFF_RT;
    float* asbuf  = g_scratch + OFF_AS;
    float* btbuf  = g_scratch + OFF_BT;

    // ======== P0: zero atomic buffers + projection y = x @ W1_nbr ========
    {
        float4* z4 = reinterpret_cast<float4*>(agg64s);
        int base = bk * NTHR + tid;
        float4 zz = make_float4(0.f, 0.f, 0.f, 0.f);
        z4[base] = zz; z4[base + 65536] = zz; z4[base + 131072] = zz;
    }
    #pragma unroll 1
    for (int it = 0; it < 2; it++) {
        int tl = bk + NBLK * it;
        int y = tl >> 8;
        rowgemm_tile<false, false, false>(sm.r, (tl & 255) * 16,
                                          y ? x_t : x_s, W1_nbr, nullptr, nullptr,
                                          y ? yt : ys);
    }
    grid_bar();

    // ======== P1: input-side scatters (atomics) ========
    #pragma unroll 1
    for (int graph = 0; graph < 2; graph++) {
        const float* yy  = graph ? yt : ys;
        const int*   ei  = graph ? eit : eis;
        const float* ea  = graph ? eat : eas;
        float*       agg = graph ? agg64t : agg64s;
        #pragma unroll 2
        for (int it = 0; it < 16; it++) {
            int gid = it * TOTT + bk * NTHR + tid;
            int e = gid >> 4, c = gid & 15;
            int s = ei[e], d = ei[kE + e];
            float wgt = ea[e];
            float4 v = *reinterpret_cast<const float4*>(yy + (size_t)s * 64 + c * 4);
            red4(agg + (size_t)d * 64 + c * 4, v, wgt);
        }
    }
    // raw-r s-graph scatter: BOTH steps per edge visit (index loaded once)
    #pragma unroll 2
    for (int it = 0; it < 8; it++) {
        int gid = it * TOTT + bk * NTHR + tid;
        int e = gid >> 3, c = gid & 7;
        int s = eis[e], d = eis[kE + e];
        float wgt = eas[e];
        float4 v0 = *reinterpret_cast<const float4*>(r_all + (size_t)s * 32 + c * 4);
        red4(agg32s + (size_t)d * 32 + c * 4, v0, wgt);
        float4 v1 = *reinterpret_cast<const float4*>(r_all + SZ_NTR + (size_t)s * 32 + c * 4);
        red4(agg32s + SZ_NTR + (size_t)d * 32 + c * 4, v1, wgt);
    }
    grid_bar();

    // ======== P2: root GEMM + a_s psi2 (both steps) ========
    #pragma unroll 1
    for (int it = 0; it < 2; it++) {
        int tl = bk + NBLK * it;
        int y = tl >> 8;
        rowgemm_tile<true, true, true>(sm.r, (tl & 255) * 16,
                                       y ? x_t : x_s, W1_root, b1,
                                       y ? agg64t : agg64s,
                                       y ? ht : hs);
    }
    __syncthreads();
    {
        int step = bk >> 7;
        psi2_body<4>(sm.p, (bk & 127) * 32,
                     r_all + (size_t)step * SZ_NTR, agg32s + (size_t)step * SZ_NTR,
                     W2_root, W2_nbr, b2, Wm1, bm1,
                     asbuf + (size_t)step * SZ_NTR, 1);
    }
    grid_bar();

    // ======== P3: S_hat0 = h_s @ h_t^T -- 32 rows/block, 4 rows/warp ========
    {
        int b  = bk >> 5;
        int s0 = ((bk >> 1) & 15) * 32;
        int th = bk & 1;

        const float4* hsb4 = reinterpret_cast<const float4*>(hs + ((size_t)b * kN + s0) * kDH);
        for (int i = tid; i < 512; i += NTHR)
            *reinterpret_cast<float4*>(&sm.g.hsS[i >> 4][(i & 15) * 4]) = hsb4[i];

        #pragma unroll 1
        for (int tt2 = 0; tt2 < 2; tt2++) {
            int tt = th * 2 + tt2;
            __syncthreads();
            const float4* htb4 = reinterpret_cast<const float4*>(ht + ((size_t)b * kN + tt * 128) * kDH);
            for (int i = tid; i < 2048; i += NTHR)
                *reinterpret_cast<float4*>(&sm.g.htS[i >> 4][(i & 15) * 4]) = htb4[i];
            __syncthreads();

            uint64_t acc2[4][4];
            #pragma unroll
            for (int r = 0; r < 4; r++)
                #pragma unroll
                for (int m = 0; m < 4; m++) acc2[r][m] = 0ull;

            #pragma unroll 2
            for (int k4 = 0; k4 < 16; k4++) {
                uint64_t a0[4], a1[4];
                #pragma unroll
                for (int r = 0; r < 4; r++)
                    lds_v2u64(a0[r], a1[r], &sm.g.hsS[4 * w + r][k4 * 4]);
                #pragma unroll
                for (int m = 0; m < 4; m++) {
                    uint64_t h0, h1;
                    lds_v2u64(h0, h1, &sm.g.htS[lane + 32 * m][k4 * 4]);
                    #pragma unroll
                    for (int r = 0; r < 4; r++) {
                        ffma2(acc2[r][m], a0[r], h0);
                        ffma2(acc2[r][m], a1[r], h1);
                    }
                }
            }

            #pragma unroll
            for (int r = 0; r < 4; r++) {
                float* sh = Shat + (size_t)(b * kN + s0 + 4 * w + r) * kN + tt * 128;
                #pragma unroll
                for (int m = 0; m < 4; m++) sh[32 * m + lane] = unpack_add(acc2[r][m]);
            }
        }
    }
    grid_bar();

    // ======== SM0: softmax(Shat) -> outS0 (= S_0 output AND step-0 S) ======
    softmax_rows(Shat, outS0, gw, lane);
    grid_bar();

    // ======== consensus steps ========
    #pragma unroll 1
    for (int step = 0; step < 2; step++) {
        const float* Ssrc = step ? Snorm : outS0;
        const float* rsk  = r_all + (size_t)step * SZ_NTR;
        const float* ask  = asbuf + (size_t)step * SZ_NTR;

        // ---- A: zero agg32t + rt = S^T @ r_s (packed f32x2) ----
        {
            int gid = bk * NTHR + tid;
            reinterpret_cast<float4*>(agg32t)[gid & 32767] =
                make_float4(0.f, 0.f, 0.f, 0.f);
        }
        {
            int b = bk >> 5;
            int t0 = (bk & 31) * 16;
            const float* Sb = Ssrc + (size_t)b * kN * kN;
            const float* Rb = rsk + (size_t)b * kN * kR;
            int t_ = tid & 15, rp = tid >> 4;

            uint64_t accA = 0ull, accB = 0ull;
            #pragma unroll 1
            for (int ks = 0; ks < 8; ks++) {
                __syncthreads();
                {
                    int s = tid >> 2, t4 = tid & 3;
                    float4 v = *reinterpret_cast<const float4*>(
                        &Sb[(size_t)(ks * 64 + s) * kN + t0 + t4 * 4]);
                    sm.a.St[t4 * 4 + 0][s] = v.x;
                    sm.a.St[t4 * 4 + 1][s] = v.y;
                    sm.a.St[t4 * 4 + 2][s] = v.z;
                    sm.a.St[t4 * 4 + 3][s] = v.w;
                }
                #pragma unroll
                for (int i = tid; i < 512; i += NTHR) {
                    int s = i >> 3, r4 = i & 7;
                    float4 v = *reinterpret_cast<const float4*>(
                        &Rb[(size_t)(ks * 64 + s) * kR + r4 * 4]);
                    sm.a.Rt[r4 * 4 + 0][s] = v.x;
                    sm.a.Rt[r4 * 4 + 1][s] = v.y;
                    sm.a.Rt[r4 * 4 + 2][s] = v.z;
                    sm.a.Rt[r4 * 4 + 3][s] = v.w;
                }
                __syncthreads();
                #pragma unroll 4
                for (int k4 = 0; k4 < 16; k4++) {
                    uint64_t s0p, s1p, ra0, ra1, rb0, rb1;
                    lds_v2u64(s0p, s1p, &sm.a.St[t_][k4 * 4]);
                    lds_v2u64(ra0, ra1, &sm.a.Rt[2 * rp][k4 * 4]);
                    lds_v2u64(rb0, rb1, &sm.a.Rt[2 * rp + 1][k4 * 4]);
                    ffma2(accA, s0p, ra0);
                    ffma2(accA, s1p, ra1);
                    ffma2(accB, s0p, rb0);
                    ffma2(accB, s1p, rb1);
                }
            }
            float* rt0 = rtbuf + ((size_t)b * kN + t0 + t_) * kR + 2 * rp;
            *reinterpret_cast<float2*>(rt0) =
                make_float2(unpack_add(accA), unpack_add(accB));
        }
        grid_bar();

        // ---- B: scatter rt over t-graph edges ----
        #pragma unroll 2
        for (int it = 0; it < 8; it++) {
            int gid = it * TOTT + bk * NTHR + tid;
            int e = gid >> 3, c = gid & 7;
            int s = eit[e], d = eit[kE + e];
            float wgt = eat[e];
            float4 v = *reinterpret_cast<const float4*>(rtbuf + (size_t)s * 32 + c * 4);
            red4(agg32t + (size_t)d * 32 + c * 4, v, wgt);
        }
        grid_bar();

        // ---- C: psi2(rt, agg) @ Wm1 -> btbuf ----
        psi2_body<2>(sm.p, bk * 16, rtbuf, agg32t, W2_root, W2_nbr, b2, Wm1,
                     nullptr, btbuf, 0);
        grid_bar();

        // ---- D: mlp + S_hat add -- 32 rows/block, 4 rows/warp ----
        {
            int b  = bk >> 5;
            int s0 = ((bk >> 1) & 15) * 32;
            int th = bk & 1;
            float bm2v = bm2[0];

            if (tid < 32) sm.d.w2[tid] = Wm2[tid];
            const float4* Ab4 = reinterpret_cast<const float4*>(ask + ((size_t)b * kN + s0) * kR);
            for (int i = tid; i < 256; i += NTHR)
                *reinterpret_cast<float4*>(&sm.d.Asm[i >> 3][(i & 7) * 4]) = Ab4[i];

            #pragma unroll 1
            for (int tt2 = 0; tt2 < 2; tt2++) {
                int tt = th * 2 + tt2;
                __syncthreads();
                const float4* Bb4 = reinterpret_cast<const float4*>(btbuf + ((size_t)b * kN + tt * 128) * kR);
                for (int i = tid; i < 1024; i += NTHR)
                    *reinterpret_cast<float4*>(&sm.d.Bsm[i >> 3][(i & 7) * 4]) = Bb4[i];
                __syncthreads();

                float acc[4][4];
                #pragma unroll
                for (int r = 0; r < 4; r++)
                    #pragma unroll
                    for (int m = 0; m < 4; m++) acc[r][m] = 0.f;

                #pragma unroll 2
                for (int r4 = 0; r4 < 8; r4++) {
                    float4 ww = *reinterpret_cast<const float4*>(&sm.d.w2[r4 * 4]);
                    float4 av[4];
                    #pragma unroll
                    for (int r = 0; r < 4; r++)
                        av[r] = *reinterpret_cast<const float4*>(&sm.d.Asm[4 * w + r][r4 * 4]);
                    #pragma unroll
                    for (int m = 0; m < 4; m++) {
                        float4 bv = *reinterpret_cast<const float4*>(&sm.d.Bsm[lane + 32 * m][r4 * 4]);
                        #pragma unroll
                        for (int r = 0; r < 4; r++) {
                            float d;
                            d = fmaxf(av[r].x - bv.x, 0.f); acc[r][m] = fmaf(d, ww.x, acc[r][m]);
                            d = fmaxf(av[r].y - bv.y, 0.f); acc[r][m] = fmaf(d, ww.y, acc[r][m]);
                            d = fmaxf(av[r].z - bv.z, 0.f); acc[r][m] = fmaf(d, ww.z, acc[r][m]);
                            d = fmaxf(av[r].w - bv.w, 0.f); acc[r][m] = fmaf(d, ww.w, acc[r][m]);
                        }
                    }
                }

                #pragma unroll
                for (int r = 0; r < 4; r++) {
                    float* sh = Shat + (size_t)(b * kN + s0 + 4 * w + r) * kN + tt * 128;
                    #pragma unroll
                    for (int m = 0; m < 4; m++) {
                        int t = 32 * m + lane;
                        sh[t] = sh[t] + acc[r][m] + bm2v;   // raw updated S_hat
                    }
                }
            }
        }
        grid_bar();

        // ---- SM: softmax(updated Shat) -> Snorm (step0) / outSL (step1) ----
        softmax_rows(Shat, step ? outSL : Snorm, gw, lane);
        if (step == 0) grid_bar();
    }
}

// ---------------------------------------------------------------------------
// Host launch (ONE kernel)
// ---------------------------------------------------------------------------
extern "C" void kernel_launch(void* const* d_in, const int* in_sizes, int n_in,
                              void* d_out, int out_size)
{
    (void)in_sizes; (void)n_in; (void)out_size;
    const float* x_s     = (const float*)d_in[0];
    const int*   ei_s    = (const int*)  d_in[1];
    const float* ea_s    = (const float*)d_in[2];
    const float* x_t     = (const float*)d_in[4];
    const int*   ei_t    = (const int*)  d_in[5];
    const float* ea_t    = (const float*)d_in[6];
    const float* r_all   = (const float*)d_in[8];
    const float* W1_root = (const float*)d_in[9];
    const float* W1_nbr  = (const float*)d_in[10];
    const float* b1      = (const float*)d_in[11];
    const float* W2_root = (const float*)d_in[12];
    const float* W2_nbr  = (const float*)d_in[13];
    const float* b2      = (const float*)d_in[14];
    const float* Wm1     = (const float*)d_in[15];
    const float* bm1     = (const float*)d_in[16];
    const float* Wm2     = (const float*)d_in[17];
    const float* bm2     = (const float*)d_in[18];

    float* outS0 = (float*)d_out;
    float* outSL = outS0 + SZ_S;

    mega_kernel<<<NBLK, NTHR>>>(x_s, x_t, ei_s, ea_s, ei_t, ea_t, r_all,
                                W1_root, W1_nbr, b1, W2_root, W2_nbr, b2,
                                Wm1, bm1, Wm2, bm2, outS0, outSL);
}